// round 14
// baseline (speedup 1.0000x reference)
#include <cuda_runtime.h>
#include <cuda_bf16.h>
#include <cstdint>

// ============================================================================
// Problem constants
// ============================================================================
namespace {
constexpr int Bn = 8;
constexpr int Sn = 1024;
constexpr int Dn = 512;
constexpr int Hn = 8;
constexpr int Mproj = Bn * Sn;                                   // 8192

__device__ float g_vr[(long long)Bn * Hn * Sn * 64];    // planar V fp32
__device__ float g_vi[(long long)Bn * Hn * Sn * 64];
__device__ float2 g_o[(long long)Bn * Sn * Dn];         // attn out [B,S,D]
__device__ __nv_bfloat16 g_x2q[(long long)Mproj * 2048];  // act hi|lo per proj
__device__ __nv_bfloat16 g_x2k[(long long)Mproj * 2048];
__device__ __nv_bfloat16 g_x2v[(long long)Mproj * 2048];
__device__ __nv_bfloat16 g_x2o[(long long)Mproj * 2048];
__device__ __nv_bfloat16 g_w2q[(long long)1024 * 2048];   // wgt hi|lo per proj
__device__ __nv_bfloat16 g_w2k[(long long)1024 * 2048];
__device__ __nv_bfloat16 g_w2v[(long long)1024 * 2048];
__device__ __nv_bfloat16 g_w2o[(long long)1024 * 2048];
__device__ __nv_bfloat16 g_qb[(long long)64 * 1024 * 256];  // Q score-operand
__device__ __nv_bfloat16 g_kb[(long long)64 * 2048 * 256];  // K: re rows | im rows
__device__ __nv_bfloat16 g_vb[(long long)64 * 128 * 2048];  // V natural operand
}

// ============================================================================
// Base-target PTX helpers
// ============================================================================
__device__ __forceinline__ uint32_t smem_u32(const void* p) {
    uint32_t a;
    asm("{ .reg .u64 t; cvta.to.shared.u64 t, %1; cvt.u32.u64 %0, t; }"
        : "=r"(a) : "l"(p));
    return a;
}
__device__ __forceinline__ uint32_t sw128(uint32_t off) {
    return off ^ ((off >> 3) & 0x70);
}
#define LDMX4(r, addr)                                                        \
    asm volatile("ldmatrix.sync.aligned.m8n8.x4.shared.b16 {%0,%1,%2,%3}, [%4];" \
        : "=r"((r)[0]), "=r"((r)[1]), "=r"((r)[2]), "=r"((r)[3]) : "r"(addr))
__device__ __forceinline__ void mma_16816(float* d, const uint32_t* a,
                                          uint32_t b0, uint32_t b1) {
    asm volatile(
        "mma.sync.aligned.m16n8k16.row.col.f32.bf16.bf16.f32 "
        "{%0,%1,%2,%3}, {%4,%5,%6,%7}, {%8,%9}, {%0,%1,%2,%3};"
        : "+f"(d[0]), "+f"(d[1]), "+f"(d[2]), "+f"(d[3])
        : "r"(a[0]), "r"(a[1]), "r"(a[2]), "r"(a[3]), "r"(b0), "r"(b1));
}
#define CP_ASYNC16(dst, src) \
    asm volatile("cp.async.cg.shared.global [%0], [%1], 16;" :: "r"(dst), "l"(src))
#define CP_COMMIT()     asm volatile("cp.async.commit_group;" ::: "memory")
#define CP_WAIT(n)      asm volatile("cp.async.wait_group %0;" :: "n"(n) : "memory")

namespace {
constexpr int SM_BUF = 32768;                // A(16K)+B(16K) per buffer
constexpr int SM_TOTAL = 2 * SM_BUF + 1024;
constexpr int SMF_TOTAL = 131072 + 1024;     // fmha: Q 64K + K 32K + V 32K
}

__device__ __forceinline__ uint4 pack8(const __nv_bfloat16* v) {
    union { __nv_bfloat16 b[8]; uint4 u; } P;
#pragma unroll
    for (int i = 0; i < 8; i++) P.b[i] = v[i];
    return P.u;
}
__device__ __forceinline__ uint32_t pack2(float x, float y, float& lx, float& ly) {
    __nv_bfloat16 hx = __float2bfloat16_rn(x);
    __nv_bfloat16 hy = __float2bfloat16_rn(y);
    lx = x - __bfloat162float(hx);
    ly = y - __bfloat162float(hy);
    unsigned short ux = *reinterpret_cast<unsigned short*>(&hx);
    unsigned short uy = *reinterpret_cast<unsigned short*>(&hy);
    return (uint32_t)ux | ((uint32_t)uy << 16);
}
__device__ __forceinline__ uint32_t pack2n(float x, float y) {
    __nv_bfloat16 hx = __float2bfloat16_rn(x);
    __nv_bfloat16 hy = __float2bfloat16_rn(y);
    unsigned short ux = *reinterpret_cast<unsigned short*>(&hx);
    unsigned short uy = *reinterpret_cast<unsigned short*>(&hy);
    return (uint32_t)ux | ((uint32_t)uy << 16);
}

// ============================================================================
// Projection GEMM — warp tile 64x64, 4 warps (2x2), 128 threads, 2 CTAs/SM.
// Rationale (R13 ncu): L1 56.6% >= tensor 52.2% -> LDSM-bound. 64x64 warp
// tile raises MMA:LDSM from 2.67 to 4.0 (chunk smem reads 96KB -> 64KB).
// Same chunk-64 cp.async pipeline; epilogue math unchanged.
//   omode 0: Q -> g_qb; 1: K -> g_kb (re|im rows); 2: V planar; 3: d_out
// ============================================================================
__device__ __forceinline__ void store_proj_rt(int omode, float v, int m, int n,
    __nv_bfloat16* qb, __nv_bfloat16* kb, float* f0, float* f1)
{
    const int comp = n >> 9, f = n & 511, hh = f >> 6, dh = f & 63;
    if (omode == 3) {
        f0[(size_t)m * 1024 + (size_t)f * 2 + comp] = v;
        return;
    }
    const int z = ((m >> 10) << 3) + hh;
    const int s = m & 1023;
    if (omode == 2) {
        (comp ? f1 : f0)[((size_t)z * 1024 + s) * 64 + dh] = v;
        return;
    }
    const __nv_bfloat16 h = __float2bfloat16_rn(v);
    const __nv_bfloat16 l = __float2bfloat16_rn(v - __bfloat162float(h));
    if (omode == 0) {
        const size_t base = ((size_t)z * 1024 + s) * 256 + comp * 64 + dh;
        qb[base] = h; qb[base + 128] = l;
    } else {
        // real form at row s, imag form at row 1024+s
        const size_t r0 = ((size_t)z * 2048 + s) * 256;
        const size_t r1 = ((size_t)z * 2048 + 1024 + s) * 256;
        if (comp == 0) {
            kb[r0 + dh] = h;       kb[r0 + 128 + dh] = l;
            kb[r1 + 64 + dh] = h;  kb[r1 + 192 + dh] = l;
        } else {
            kb[r0 + 64 + dh] = __hneg(h); kb[r0 + 192 + dh] = __hneg(l);
            kb[r1 + dh] = h;       kb[r1 + 128 + dh] = l;
        }
    }
}

__global__ void __launch_bounds__(128, 2)
tgemm_kernel(const uint4* __restrict__ a0, const uint4* __restrict__ a1,
             const uint4* __restrict__ a2,
             const uint4* __restrict__ w0, const uint4* __restrict__ w1,
             const uint4* __restrict__ w2,
             int obase,
             float* __restrict__ f0, float* __restrict__ f1,
             __nv_bfloat16* __restrict__ qb, __nv_bfloat16* __restrict__ kb)
{
    extern __shared__ char smem[];
    const uint32_t sbase = (smem_u32(smem) + 1023) & ~1023u;
    const int tid = threadIdx.x;
    const int lane = tid & 31, wid = tid >> 5;
    const int wm = wid & 1, wn = wid >> 1;        // 2 x 2 warp grid
    const int m0 = blockIdx.y * 128, n0 = blockIdx.x * 128;
    const int zz = blockIdx.z;
    const int omode = obase + zz;
    const uint4* A2 = (zz == 0) ? a0 : (zz == 1) ? a1 : a2;
    const uint4* B2 = (zz == 0) ? w0 : (zz == 1) ? w1 : w2;

    float acc[4][8][4];
#pragma unroll
    for (int i = 0; i < 4; i++)
#pragma unroll
        for (int j = 0; j < 8; j++)
#pragma unroll
            for (int k = 0; k < 4; k++) acc[i][j][k] = 0.f;

    auto issue_chunk = [&](int c, int buf) {
        const int pass = c >> 4;
        const int kc = (c & 15) << 6;
        const int ca = (kc + ((pass == 1) ? 1024 : 0)) >> 3;
        const int cb = (kc + ((pass == 2) ? 1024 : 0)) >> 3;
        const uint32_t ab = sbase + buf * SM_BUF;
        const uint32_t bb = ab + 16384;
#pragma unroll
        for (int i = 0; i < 8; i++) {
            const int lin = tid + 128 * i;          // 0..1023
            const int row = lin >> 3, seg = lin & 7;
            const uint32_t off = sw128((uint32_t)(row * 128 + seg * 16));
            CP_ASYNC16(ab + off, &A2[(size_t)(m0 + row) * 256 + ca + seg]);
            CP_ASYNC16(bb + off, &B2[(size_t)(n0 + row) * 256 + cb + seg]);
        }
        CP_COMMIT();
    };

    constexpr int NC = 48;
    issue_chunk(0, 0);
    for (int c = 0; c < NC; c++) {
        const int buf = c & 1;
        if (c + 1 < NC) { issue_chunk(c + 1, buf ^ 1); CP_WAIT(1); }
        else            { CP_WAIT(0); }
        __syncthreads();
        const uint32_t ab = sbase + buf * SM_BUF;
        const uint32_t bb = ab + 16384;
#pragma unroll
        for (int kk = 0; kk < 4; kk++) {
            uint32_t af[4][4];
#pragma unroll
            for (int mt = 0; mt < 4; mt++) {
                const int row = wm * 64 + mt * 16 + (lane & 15);
                LDMX4(af[mt], ab + sw128((uint32_t)(row * 128 + kk * 32 + (lane >> 4) * 16)));
            }
            uint32_t bfr[4][4];
#pragma unroll
            for (int p = 0; p < 4; p++) {
                const int row = wn * 64 + p * 16 + (lane & 15);
                LDMX4(bfr[p], bb + sw128((uint32_t)(row * 128 + kk * 32 + (lane >> 4) * 16)));
            }
#pragma unroll
            for (int mt = 0; mt < 4; mt++)
#pragma unroll
                for (int nt = 0; nt < 8; nt++)
                    mma_16816(acc[mt][nt], af[mt],
                              bfr[nt >> 1][nt & 1], bfr[nt >> 1][(nt & 1) + 2]);
        }
        __syncthreads();
    }

    const int qrow = lane >> 2, qcol = (lane & 3) * 2;
#pragma unroll
    for (int mt = 0; mt < 4; mt++)
#pragma unroll
        for (int nt = 0; nt < 8; nt++)
#pragma unroll
            for (int h2 = 0; h2 < 2; h2++) {
                const int m = m0 + wm * 64 + mt * 16 + qrow + 8 * h2;
                const int n = n0 + wn * 64 + nt * 8 + qcol;
                store_proj_rt(omode, acc[mt][nt][2 * h2],     m, n,     qb, kb, f0, f1);
                store_proj_rt(omode, acc[mt][nt][2 * h2 + 1], m, n + 1, qb, kb, f0, f1);
            }
}

// ============================================================================
// Fused flash attention (R8 version, verbatim): register-resident P.
// ============================================================================
__global__ void __launch_bounds__(256, 1)
fmha_kernel(const uint4* __restrict__ qb4, const uint4* __restrict__ kb4,
            const uint4* __restrict__ vb4, float2* __restrict__ out)
{
    extern __shared__ char smem[];
    const uint32_t sb = (smem_u32(smem) + 1023) & ~1023u;
    const int tid = threadIdx.x;
    const int lane = tid & 31, w = tid >> 5;
    const int qrow = lane >> 2, ql = lane & 3;
    const int z = blockIdx.y;
    const int m0 = blockIdx.x * 128;

    const uint4* Qz = qb4 + ((size_t)z * 1024 + m0) * 32;
    const uint4* Kz = kb4 + (size_t)z * 2048 * 32;
    const uint4* Vz = vb4 + (size_t)z * 128 * 256;

    const uint32_t QOFF = sb;
    const uint32_t KOFF = sb + 65536;
    const uint32_t VOFF = sb + 98304;

#pragma unroll
    for (int i = 0; i < 16; i++) {
        const int lin = tid + 256 * i;
        const int row = lin >> 5, u = lin & 31;
        CP_ASYNC16(QOFF + (u >> 3) * 16384 + sw128((uint32_t)(row * 128 + (u & 7) * 16)),
                   Qz + row * 32 + u);
    }
    CP_COMMIT();

    float accO1[16][4], accO2[16][4];
#pragma unroll
    for (int i = 0; i < 16; i++)
#pragma unroll
        for (int j = 0; j < 4; j++) { accO1[i][j] = 0.f; accO2[i][j] = 0.f; }
    float mr[2] = {-1e30f, -1e30f}, mi_[2] = {-1e30f, -1e30f};
    float lr[2] = {0.f, 0.f}, li[2] = {0.f, 0.f};

    auto issueK = [&](int c, int kb) {
        const int g = (c < 4) ? (c & 1) : (c - 2);
        const uint32_t kbuf = KOFF + (c & 1) * 16384;
#pragma unroll
        for (int i = 0; i < 4; i++) {
            const int lin = tid + 256 * i;
            const int row = lin >> 3, seg = lin & 7;
            const int grow = kb * 64 + (row & 63) + ((row >> 6) << 10);
            CP_ASYNC16(kbuf + sw128((uint32_t)(row * 128 + seg * 16)),
                       Kz + (size_t)grow * 32 + g * 8 + seg);
        }
        CP_COMMIT();
    };

    constexpr float SC = 0.125f;

    for (int kb = 0; kb < 16; kb++) {
#pragma unroll
        for (int i = 0; i < 8; i++) {
            const int lin = tid + 256 * i;
            const int half = lin >> 10, r2 = lin & 1023;
            const int row = r2 >> 3, seg = r2 & 7;
            CP_ASYNC16(VOFF + half * 16384 + sw128((uint32_t)(row * 128 + seg * 16)),
                       Vz + row * 256 + half * 128 + kb * 8 + seg);
        }
        CP_COMMIT();
        issueK(0, kb);

        float accS[16][4];
#pragma unroll
        for (int i = 0; i < 16; i++)
#pragma unroll
            for (int j = 0; j < 4; j++) accS[i][j] = 0.f;

        for (int c = 0; c < 6; c++) {
            CP_WAIT(0);
            __syncthreads();
            if (c < 5) issueK(c + 1, kb);
            const int pA = (c < 4) ? c : (c - 4);
            const uint32_t kbuf = KOFF + (c & 1) * 16384;
            const uint32_t qbase = QOFF + pA * 16384;
#pragma unroll
            for (int kk = 0; kk < 4; kk++) {
                uint32_t af[4];
                LDMX4(af, qbase + sw128((uint32_t)((16 * w + (lane & 15)) * 128
                                                   + kk * 32 + (lane >> 4) * 16)));
#pragma unroll
                for (int ntp = 0; ntp < 8; ntp++) {
                    uint32_t bfr[4];
                    LDMX4(bfr, kbuf + sw128((uint32_t)((ntp * 16 + (lane & 15)) * 128
                                                       + kk * 32 + (lane >> 4) * 16)));
                    mma_16816(accS[2 * ntp],     af, bfr[0], bfr[2]);
                    mma_16816(accS[2 * ntp + 1], af, bfr[1], bfr[3]);
                }
            }
        }

        float fr[2], fi[2];
#pragma unroll
        for (int g2 = 0; g2 < 2; g2++) {
            float a = -1e30f, b = -1e30f;
#pragma unroll
            for (int nt = 0; nt < 8; nt++) {
                a = fmaxf(a, fmaxf(accS[nt][2 * g2], accS[nt][2 * g2 + 1]));
                b = fmaxf(b, fmaxf(accS[nt + 8][2 * g2], accS[nt + 8][2 * g2 + 1]));
            }
            a = fmaxf(a, __shfl_xor_sync(0xffffffffu, a, 1));
            a = fmaxf(a, __shfl_xor_sync(0xffffffffu, a, 2));
            b = fmaxf(b, __shfl_xor_sync(0xffffffffu, b, 1));
            b = fmaxf(b, __shfl_xor_sync(0xffffffffu, b, 2));
            a *= SC; b *= SC;
            const float nmr = fmaxf(mr[g2], a);
            const float nmi = fmaxf(mi_[g2], b);
            fr[g2] = __expf(mr[g2] - nmr);
            fi[g2] = __expf(mi_[g2] - nmi);
            mr[g2] = nmr; mi_[g2] = nmi;
        }
#pragma unroll
        for (int nt = 0; nt < 16; nt++) {
            accO1[nt][0] *= fr[0]; accO1[nt][1] *= fr[0];
            accO1[nt][2] *= fr[1]; accO1[nt][3] *= fr[1];
            accO2[nt][0] *= fi[0]; accO2[nt][1] *= fi[0];
            accO2[nt][2] *= fi[1]; accO2[nt][3] *= fi[1];
        }

        uint32_t prh[4][4], pih[4][4];
        float sr0 = 0.f, sr1 = 0.f, si0 = 0.f, si1 = 0.f;
#pragma unroll
        for (int kk2 = 0; kk2 < 4; kk2++) {
            uint32_t prl[4], pil[4];
#pragma unroll
            for (int half = 0; half < 2; half++) {
                {
                    const int nt = 2 * kk2 + half;
                    const float p0 = __expf(accS[nt][0] * SC - mr[0]);
                    const float p1 = __expf(accS[nt][1] * SC - mr[0]);
                    const float p2 = __expf(accS[nt][2] * SC - mr[1]);
                    const float p3 = __expf(accS[nt][3] * SC - mr[1]);
                    sr0 += p0 + p1; sr1 += p2 + p3;
                    float l0, l1, l2, l3;
                    prh[kk2][2 * half]     = pack2(p0, p1, l0, l1);
                    prh[kk2][2 * half + 1] = pack2(p2, p3, l2, l3);
                    prl[2 * half]          = pack2n(l0, l1);
                    prl[2 * half + 1]      = pack2n(l2, l3);
                }
                {
                    const int nt = 8 + 2 * kk2 + half;
                    const float p0 = __expf(accS[nt][0] * SC - mi_[0]);
                    const float p1 = __expf(accS[nt][1] * SC - mi_[0]);
                    const float p2 = __expf(accS[nt][2] * SC - mi_[1]);
                    const float p3 = __expf(accS[nt][3] * SC - mi_[1]);
                    si0 += p0 + p1; si1 += p2 + p3;
                    float l0, l1, l2, l3;
                    pih[kk2][2 * half]     = pack2(p0, p1, l0, l1);
                    pih[kk2][2 * half + 1] = pack2(p2, p3, l2, l3);
                    pil[2 * half]          = pack2n(l0, l1);
                    pil[2 * half + 1]      = pack2n(l2, l3);
                }
            }
#pragma unroll
            for (int ntp = 0; ntp < 8; ntp++) {
                uint32_t bfr[4];
                LDMX4(bfr, VOFF + sw128((uint32_t)((ntp * 16 + (lane & 15)) * 128
                                                   + kk2 * 32 + (lane >> 4) * 16)));
                mma_16816(accO1[2 * ntp],     prh[kk2], bfr[0], bfr[2]);
                mma_16816(accO1[2 * ntp + 1], prh[kk2], bfr[1], bfr[3]);
                mma_16816(accO1[2 * ntp],     prl,      bfr[0], bfr[2]);
                mma_16816(accO1[2 * ntp + 1], prl,      bfr[1], bfr[3]);
                mma_16816(accO2[2 * ntp],     pih[kk2], bfr[0], bfr[2]);
                mma_16816(accO2[2 * ntp + 1], pih[kk2], bfr[1], bfr[3]);
                mma_16816(accO2[2 * ntp],     pil,      bfr[0], bfr[2]);
                mma_16816(accO2[2 * ntp + 1], pil,      bfr[1], bfr[3]);
            }
        }
        sr0 += __shfl_xor_sync(0xffffffffu, sr0, 1);
        sr0 += __shfl_xor_sync(0xffffffffu, sr0, 2);
        sr1 += __shfl_xor_sync(0xffffffffu, sr1, 1);
        sr1 += __shfl_xor_sync(0xffffffffu, sr1, 2);
        si0 += __shfl_xor_sync(0xffffffffu, si0, 1);
        si0 += __shfl_xor_sync(0xffffffffu, si0, 2);
        si1 += __shfl_xor_sync(0xffffffffu, si1, 1);
        si1 += __shfl_xor_sync(0xffffffffu, si1, 2);
        lr[0] = lr[0] * fr[0] + sr0;  lr[1] = lr[1] * fr[1] + sr1;
        li[0] = li[0] * fi[0] + si0;  li[1] = li[1] * fi[1] + si1;

#pragma unroll
        for (int kk2 = 0; kk2 < 4; kk2++)
#pragma unroll
            for (int ntp = 0; ntp < 8; ntp++) {
                uint32_t bfr[4];
                LDMX4(bfr, VOFF + 16384 + sw128((uint32_t)((ntp * 16 + (lane & 15)) * 128
                                                           + kk2 * 32 + (lane >> 4) * 16)));
                mma_16816(accO1[2 * ntp],     prh[kk2], bfr[0], bfr[2]);
                mma_16816(accO1[2 * ntp + 1], prh[kk2], bfr[1], bfr[3]);
                mma_16816(accO2[2 * ntp],     pih[kk2], bfr[0], bfr[2]);
                mma_16816(accO2[2 * ntp + 1], pih[kk2], bfr[1], bfr[3]);
            }

        __syncthreads();
    }

#pragma unroll
    for (int g2 = 0; g2 < 2; g2++) {
        const float ivr = 1.f / lr[g2];
        const float ivi = 1.f / li[g2];
        const int s = m0 + 16 * w + qrow + 8 * g2;
#pragma unroll
        for (int nt = 0; nt < 16; nt++) {
            const int dh = 4 * nt + ql;
            const float o_r = accO1[nt][2 * g2]     * ivr - accO2[nt][2 * g2 + 1] * ivi;
            const float o_i = accO1[nt][2 * g2 + 1] * ivr + accO2[nt][2 * g2]     * ivi;
            out[((size_t)(z >> 3) * 1024 + s) * 512 + (z & 7) * 64 + dh] =
                make_float2(o_r, o_i);
        }
    }
}

// ============================================================================
// V operand: planar fp32 [z][s][dh] -> g_vb [z][n=128][2048]
// ============================================================================
__global__ void __launch_bounds__(256)
vconv_kernel(const float* __restrict__ vr, const float* __restrict__ vi,
             __nv_bfloat16* __restrict__ vb)
{
    __shared__ float tile[2][64][65];
    const int z = blockIdx.y, s0 = blockIdx.x * 64;
    const int tid = threadIdx.x;
#pragma unroll
    for (int i = 0; i < 16; i++) {
        const int idx = tid + 256 * i;
        const int row = idx >> 6, c = idx & 63;
        const size_t g = ((size_t)z * 1024 + s0 + row) * 64 + c;
        tile[0][row][c] = vr[g];
        tile[1][row][c] = vi[g];
    }
    __syncthreads();
    const int r = tid >> 1, h4 = tid & 1;
    const int dh = r >> 1, ci = r & 1;
    __nv_bfloat16 hb[32], lb[32];
#pragma unroll
    for (int j = 0; j < 32; j++) {
        const int t = h4 * 32 + j;
        const float v = ci ? tile[1][t][dh] : tile[0][t][dh];
        const __nv_bfloat16 h = __float2bfloat16_rn(v);
        hb[j] = h;
        lb[j] = __float2bfloat16_rn(v - __bfloat162float(h));
    }
    const size_t base = ((size_t)z * 128 + r) * 2048 + s0 + h4 * 32;
#pragma unroll
    for (int u = 0; u < 4; u++) {
        *(uint4*)(vb + base + 8 * u) = pack8(hb + 8 * u);
        *(uint4*)(vb + base + 1024 + 8 * u) = pack8(lb + 8 * u);
    }
}

// ============================================================================
// fp32 -> bf16 hi/lo conversions (z-batched over up to 3 tensors)
// ============================================================================
__global__ void __launch_bounds__(256)
convx_kernel(const float2* __restrict__ in0, const float2* __restrict__ in1,
             const float2* __restrict__ in2,
             __nv_bfloat16* __restrict__ o0, __nv_bfloat16* __restrict__ o1,
             __nv_bfloat16* __restrict__ o2)
{
    const int zz = blockIdx.y;
    const float2* in = (zz == 0) ? in0 : (zz == 1) ? in1 : in2;
    __nv_bfloat16* out = (zz == 0) ? o0 : (zz == 1) ? o1 : o2;
    const int idx = blockIdx.x * 256 + threadIdx.x;
    const int m = idx >> 7;
    const int comp = (idx >> 6) & 1;
    const int f8 = (idx & 63) * 8;
    const float2* src = in + (long long)m * 512 + f8;
    __nv_bfloat16 hi[8], lo[8];
#pragma unroll
    for (int j = 0; j < 8; j++) {
        const float x = comp ? src[j].y : src[j].x;
        const __nv_bfloat16 h = __float2bfloat16_rn(x);
        hi[j] = h;
        lo[j] = __float2bfloat16_rn(x - __bfloat162float(h));
    }
    __nv_bfloat16* dst = out + (long long)m * 2048 + comp * 512 + f8;
    *(uint4*)dst = pack8(hi);
    *(uint4*)(dst + 1024) = pack8(lo);
}

__global__ void __launch_bounds__(256)
convw_kernel(const float* __restrict__ r0, const float* __restrict__ i0,
             const float* __restrict__ r1, const float* __restrict__ i1,
             const float* __restrict__ r2, const float* __restrict__ i2,
             __nv_bfloat16* __restrict__ o0, __nv_bfloat16* __restrict__ o1,
             __nv_bfloat16* __restrict__ o2)
{
    const int zz = blockIdx.y;
    const float* wr = (zz == 0) ? r0 : (zz == 1) ? r1 : r2;
    const float* wi = (zz == 0) ? i0 : (zz == 1) ? i1 : i2;
    __nv_bfloat16* out = (zz == 0) ? o0 : (zz == 1) ? o1 : o2;
    const int idx = blockIdx.x * 256 + threadIdx.x;
    const int n = idx >> 7;
    const int half = (idx >> 6) & 1;
    const int f8 = (idx & 63) * 8;
    const float* src;
    float sgn = 1.f;
    if (n < 512) { src = (half ? wi : wr) + (long long)n * 512; if (half) sgn = -1.f; }
    else         { src = (half ? wr : wi) + (long long)(n - 512) * 512; }
    __nv_bfloat16 hi[8], lo[8];
#pragma unroll
    for (int j = 0; j < 8; j++) {
        const float x = sgn * src[f8 + j];
        const __nv_bfloat16 h = __float2bfloat16_rn(x);
        hi[j] = h;
        lo[j] = __float2bfloat16_rn(x - __bfloat162float(h));
    }
    __nv_bfloat16* dst = out + (long long)n * 2048 + half * 512 + f8;
    *(uint4*)dst = pack8(hi);
    *(uint4*)(dst + 1024) = pack8(lo);
}

// ============================================================================
extern "C" void kernel_launch(void* const* d_in, const int* in_sizes, int n_in,
                              void* d_out, int out_size)
{
    (void)in_sizes; (void)n_in; (void)out_size;
    const float2* Qin = (const float2*)d_in[0];
    const float2* Kin = (const float2*)d_in[1];
    const float2* Vin = (const float2*)d_in[2];
    const float* wq_r = (const float*)d_in[3];
    const float* wq_i = (const float*)d_in[4];
    const float* wk_r = (const float*)d_in[5];
    const float* wk_i = (const float*)d_in[6];
    const float* wv_r = (const float*)d_in[7];
    const float* wv_i = (const float*)d_in[8];
    const float* wo_r = (const float*)d_in[9];
    const float* wo_i = (const float*)d_in[10];

    float *vr, *vi;
    float2 *o;
    __nv_bfloat16 *x2q, *x2k, *x2v, *x2o, *w2q, *w2k, *w2v, *w2o, *qb, *kb, *vb;
    cudaGetSymbolAddress((void**)&vr, g_vr);
    cudaGetSymbolAddress((void**)&vi, g_vi);
    cudaGetSymbolAddress((void**)&o, g_o);
    cudaGetSymbolAddress((void**)&x2q, g_x2q);
    cudaGetSymbolAddress((void**)&x2k, g_x2k);
    cudaGetSymbolAddress((void**)&x2v, g_x2v);
    cudaGetSymbolAddress((void**)&x2o, g_x2o);
    cudaGetSymbolAddress((void**)&w2q, g_w2q);
    cudaGetSymbolAddress((void**)&w2k, g_w2k);
    cudaGetSymbolAddress((void**)&w2v, g_w2v);
    cudaGetSymbolAddress((void**)&w2o, g_w2o);
    cudaGetSymbolAddress((void**)&qb, g_qb);
    cudaGetSymbolAddress((void**)&kb, g_kb);
    cudaGetSymbolAddress((void**)&vb, g_vb);

    cudaFuncSetAttribute(tgemm_kernel, cudaFuncAttributeMaxDynamicSharedMemorySize, SM_TOTAL);
    cudaFuncSetAttribute(fmha_kernel, cudaFuncAttributeMaxDynamicSharedMemorySize, SMF_TOTAL);

    // --- batched input + weight conversions ---
    convx_kernel<<<dim3(4096, 3), 256>>>(Qin, Kin, Vin, x2q, x2k, x2v);
    convw_kernel<<<dim3(512, 3), 256>>>(wq_r, wq_i, wk_r, wk_i, wv_r, wv_i,
                                        w2q, w2k, w2v);
    convw_kernel<<<dim3(512, 1), 256>>>(wo_r, wo_i, nullptr, nullptr, nullptr,
                                        nullptr, w2o, nullptr, nullptr);

    // --- Q/K/V projections in ONE z-batched launch (4-warp CTAs, 2/SM) ---
    tgemm_kernel<<<dim3(8, 64, 3), 128, SM_TOTAL>>>(
        (const uint4*)x2q, (const uint4*)x2k, (const uint4*)x2v,
        (const uint4*)w2q, (const uint4*)w2k, (const uint4*)w2v,
        /*obase=*/0, vr, vi, qb, kb);

    // --- V operand transpose ---
    vconv_kernel<<<dim3(16, 64), 256>>>(vr, vi, vb);

    // --- fused attention (R8 engine) ---
    fmha_kernel<<<dim3(8, 64), 256, SMF_TOTAL>>>(
        (const uint4*)qb, (const uint4*)kb, (const uint4*)vb, o);

    // --- output projection ---
    convx_kernel<<<dim3(4096, 1), 256>>>(o, nullptr, nullptr, x2o, nullptr, nullptr);
    tgemm_kernel<<<dim3(8, 64, 1), 128, SM_TOTAL>>>(
        (const uint4*)x2o, nullptr, nullptr,
        (const uint4*)w2o, nullptr, nullptr,
        /*obase=*/3, (float*)d_out, nullptr, nullptr, nullptr);
}

// round 15
// speedup vs baseline: 1.0822x; 1.0822x over previous
#include <cuda_runtime.h>
#include <cuda_bf16.h>
#include <cstdint>

// ============================================================================
// Problem constants
// ============================================================================
namespace {
constexpr int Bn = 8;
constexpr int Sn = 1024;
constexpr int Dn = 512;
constexpr int Hn = 8;
constexpr int Mproj = Bn * Sn;                                   // 8192

__device__ float g_vr[(long long)Bn * Hn * Sn * 64];    // planar V fp32
__device__ float g_vi[(long long)Bn * Hn * Sn * 64];
__device__ float2 g_o[(long long)Bn * Sn * Dn];         // attn out [B,S,D]
__device__ __nv_bfloat16 g_x2q[(long long)Mproj * 2048];  // act hi|lo per proj
__device__ __nv_bfloat16 g_x2k[(long long)Mproj * 2048];
__device__ __nv_bfloat16 g_x2v[(long long)Mproj * 2048];
__device__ __nv_bfloat16 g_x2o[(long long)Mproj * 2048];
__device__ __nv_bfloat16 g_w2q[(long long)1024 * 2048];   // wgt hi|lo per proj
__device__ __nv_bfloat16 g_w2k[(long long)1024 * 2048];
__device__ __nv_bfloat16 g_w2v[(long long)1024 * 2048];
__device__ __nv_bfloat16 g_w2o[(long long)1024 * 2048];
__device__ __nv_bfloat16 g_qb[(long long)64 * 1024 * 256];  // Q score-operand
__device__ __nv_bfloat16 g_kb[(long long)64 * 2048 * 256];  // K: re rows | im rows
__device__ __nv_bfloat16 g_vb[(long long)64 * 128 * 2048];  // V natural operand
}

// ============================================================================
// Base-target PTX helpers
// ============================================================================
__device__ __forceinline__ uint32_t smem_u32(const void* p) {
    uint32_t a;
    asm("{ .reg .u64 t; cvta.to.shared.u64 t, %1; cvt.u32.u64 %0, t; }"
        : "=r"(a) : "l"(p));
    return a;
}
__device__ __forceinline__ uint32_t sw128(uint32_t off) {
    return off ^ ((off >> 3) & 0x70);
}
#define LDMX4(r, addr)                                                        \
    asm volatile("ldmatrix.sync.aligned.m8n8.x4.shared.b16 {%0,%1,%2,%3}, [%4];" \
        : "=r"((r)[0]), "=r"((r)[1]), "=r"((r)[2]), "=r"((r)[3]) : "r"(addr))
__device__ __forceinline__ void mma_16816(float* d, const uint32_t* a,
                                          uint32_t b0, uint32_t b1) {
    asm volatile(
        "mma.sync.aligned.m16n8k16.row.col.f32.bf16.bf16.f32 "
        "{%0,%1,%2,%3}, {%4,%5,%6,%7}, {%8,%9}, {%0,%1,%2,%3};"
        : "+f"(d[0]), "+f"(d[1]), "+f"(d[2]), "+f"(d[3])
        : "r"(a[0]), "r"(a[1]), "r"(a[2]), "r"(a[3]), "r"(b0), "r"(b1));
}
#define CP_ASYNC16(dst, src) \
    asm volatile("cp.async.cg.shared.global [%0], [%1], 16;" :: "r"(dst), "l"(src))
#define CP_COMMIT()     asm volatile("cp.async.commit_group;" ::: "memory")
#define CP_WAIT(n)      asm volatile("cp.async.wait_group %0;" :: "n"(n) : "memory")

namespace {
constexpr int SM_BUF = 32768;                // A(16K)+B(16K) per buffer
constexpr int SM_TOTAL = 2 * SM_BUF + 1024;
constexpr int SMF_TOTAL = 98304 + 1024;      // fmha64: Q 32K + K 32K + V 32K
}

__device__ __forceinline__ uint4 pack8(const __nv_bfloat16* v) {
    union { __nv_bfloat16 b[8]; uint4 u; } P;
#pragma unroll
    for (int i = 0; i < 8; i++) P.b[i] = v[i];
    return P.u;
}
__device__ __forceinline__ uint32_t pack2(float x, float y, float& lx, float& ly) {
    __nv_bfloat16 hx = __float2bfloat16_rn(x);
    __nv_bfloat16 hy = __float2bfloat16_rn(y);
    lx = x - __bfloat162float(hx);
    ly = y - __bfloat162float(hy);
    unsigned short ux = *reinterpret_cast<unsigned short*>(&hx);
    unsigned short uy = *reinterpret_cast<unsigned short*>(&hy);
    return (uint32_t)ux | ((uint32_t)uy << 16);
}
__device__ __forceinline__ uint32_t pack2n(float x, float y) {
    __nv_bfloat16 hx = __float2bfloat16_rn(x);
    __nv_bfloat16 hy = __float2bfloat16_rn(y);
    unsigned short ux = *reinterpret_cast<unsigned short*>(&hx);
    unsigned short uy = *reinterpret_cast<unsigned short*>(&hy);
    return (uint32_t)ux | ((uint32_t)uy << 16);
}

// ============================================================================
// Projection GEMM (R13 config — RF-optimal: 8 warps 2x4, warp tile 64x32,
// 256 threads, 2 CTAs/SM via 128-reg cap).
//   omode 0: Q -> g_qb; 1: K -> g_kb (re|im rows); 2: V planar; 3: d_out
// ============================================================================
__device__ __forceinline__ void store_proj_rt(int omode, float v, int m, int n,
    __nv_bfloat16* qb, __nv_bfloat16* kb, float* f0, float* f1)
{
    const int comp = n >> 9, f = n & 511, hh = f >> 6, dh = f & 63;
    if (omode == 3) {
        f0[(size_t)m * 1024 + (size_t)f * 2 + comp] = v;
        return;
    }
    const int z = ((m >> 10) << 3) + hh;
    const int s = m & 1023;
    if (omode == 2) {
        (comp ? f1 : f0)[((size_t)z * 1024 + s) * 64 + dh] = v;
        return;
    }
    const __nv_bfloat16 h = __float2bfloat16_rn(v);
    const __nv_bfloat16 l = __float2bfloat16_rn(v - __bfloat162float(h));
    if (omode == 0) {
        const size_t base = ((size_t)z * 1024 + s) * 256 + comp * 64 + dh;
        qb[base] = h; qb[base + 128] = l;
    } else {
        // real form at row s, imag form at row 1024+s
        const size_t r0 = ((size_t)z * 2048 + s) * 256;
        const size_t r1 = ((size_t)z * 2048 + 1024 + s) * 256;
        if (comp == 0) {
            kb[r0 + dh] = h;       kb[r0 + 128 + dh] = l;
            kb[r1 + 64 + dh] = h;  kb[r1 + 192 + dh] = l;
        } else {
            kb[r0 + 64 + dh] = __hneg(h); kb[r0 + 192 + dh] = __hneg(l);
            kb[r1 + dh] = h;       kb[r1 + 128 + dh] = l;
        }
    }
}

__global__ void __launch_bounds__(256, 2)
tgemm_kernel(const uint4* __restrict__ a0, const uint4* __restrict__ a1,
             const uint4* __restrict__ a2,
             const uint4* __restrict__ w0, const uint4* __restrict__ w1,
             const uint4* __restrict__ w2,
             int obase,
             float* __restrict__ f0, float* __restrict__ f1,
             __nv_bfloat16* __restrict__ qb, __nv_bfloat16* __restrict__ kb)
{
    extern __shared__ char smem[];
    const uint32_t sbase = (smem_u32(smem) + 1023) & ~1023u;
    const int tid = threadIdx.x;
    const int lane = tid & 31, wid = tid >> 5;
    const int wm = wid & 1, wn = wid >> 1;
    const int m0 = blockIdx.y * 128, n0 = blockIdx.x * 128;
    const int zz = blockIdx.z;
    const int omode = obase + zz;
    const uint4* A2 = (zz == 0) ? a0 : (zz == 1) ? a1 : a2;
    const uint4* B2 = (zz == 0) ? w0 : (zz == 1) ? w1 : w2;

    float acc[4][4][4];
#pragma unroll
    for (int i = 0; i < 4; i++)
#pragma unroll
        for (int j = 0; j < 4; j++)
#pragma unroll
            for (int k = 0; k < 4; k++) acc[i][j][k] = 0.f;

    auto issue_chunk = [&](int c, int buf) {
        const int pass = c >> 4;
        const int kc = (c & 15) << 6;
        const int ca = (kc + ((pass == 1) ? 1024 : 0)) >> 3;
        const int cb = (kc + ((pass == 2) ? 1024 : 0)) >> 3;
        const uint32_t ab = sbase + buf * SM_BUF;
        const uint32_t bb = ab + 16384;
#pragma unroll
        for (int i = 0; i < 4; i++) {
            const int lin = tid + 256 * i;
            const int row = lin >> 3, seg = lin & 7;
            const uint32_t off = sw128((uint32_t)(row * 128 + seg * 16));
            CP_ASYNC16(ab + off, &A2[(size_t)(m0 + row) * 256 + ca + seg]);
            CP_ASYNC16(bb + off, &B2[(size_t)(n0 + row) * 256 + cb + seg]);
        }
        CP_COMMIT();
    };

    constexpr int NC = 48;
    issue_chunk(0, 0);
    for (int c = 0; c < NC; c++) {
        const int buf = c & 1;
        if (c + 1 < NC) { issue_chunk(c + 1, buf ^ 1); CP_WAIT(1); }
        else            { CP_WAIT(0); }
        __syncthreads();
        const uint32_t ab = sbase + buf * SM_BUF;
        const uint32_t bb = ab + 16384;
#pragma unroll
        for (int kk = 0; kk < 4; kk++) {
            uint32_t af[4][4];
#pragma unroll
            for (int mt = 0; mt < 4; mt++) {
                const int row = wm * 64 + mt * 16 + (lane & 15);
                LDMX4(af[mt], ab + sw128((uint32_t)(row * 128 + kk * 32 + (lane >> 4) * 16)));
            }
            uint32_t bfr[2][4];
#pragma unroll
            for (int p = 0; p < 2; p++) {
                const int row = wn * 32 + p * 16 + (lane & 15);
                LDMX4(bfr[p], bb + sw128((uint32_t)(row * 128 + kk * 32 + (lane >> 4) * 16)));
            }
#pragma unroll
            for (int mt = 0; mt < 4; mt++)
#pragma unroll
                for (int nt = 0; nt < 4; nt++)
                    mma_16816(acc[mt][nt], af[mt],
                              bfr[nt >> 1][nt & 1], bfr[nt >> 1][(nt & 1) + 2]);
        }
        __syncthreads();
    }

    const int qrow = lane >> 2, qcol = (lane & 3) * 2;
#pragma unroll
    for (int mt = 0; mt < 4; mt++)
#pragma unroll
        for (int nt = 0; nt < 4; nt++)
#pragma unroll
            for (int h2 = 0; h2 < 2; h2++) {
                const int m = m0 + wm * 64 + mt * 16 + qrow + 8 * h2;
                const int n = n0 + wn * 32 + nt * 8 + qcol;
                store_proj_rt(omode, acc[mt][nt][2 * h2],     m, n,     qb, kb, f0, f1);
                store_proj_rt(omode, acc[mt][nt][2 * h2 + 1], m, n + 1, qb, kb, f0, f1);
            }
}

// ============================================================================
// Fused flash attention — 64-row CTA variant of the R8 engine.
// 4 warps (128 threads), warp w owns rows 16w..16w+15; smem 96KB -> 2 CTAs/SM.
// Per-warp mainloop, softmax, P-packing identical to R8.
// ============================================================================
__global__ void __launch_bounds__(128, 2)
fmha_kernel(const uint4* __restrict__ qb4, const uint4* __restrict__ kb4,
            const uint4* __restrict__ vb4, float2* __restrict__ out)
{
    extern __shared__ char smem[];
    const uint32_t sb = (smem_u32(smem) + 1023) & ~1023u;
    const int tid = threadIdx.x;
    const int lane = tid & 31, w = tid >> 5;      // w = 0..3
    const int qrow = lane >> 2, ql = lane & 3;
    const int z = blockIdx.y;
    const int m0 = blockIdx.x * 64;

    const uint4* Qz = qb4 + ((size_t)z * 1024 + m0) * 32;
    const uint4* Kz = kb4 + (size_t)z * 2048 * 32;
    const uint4* Vz = vb4 + (size_t)z * 128 * 256;

    const uint32_t QOFF = sb;                 // 4 panels x 8KB (64 rows)
    const uint32_t KOFF = sb + 32768;         // 2 x 16KB
    const uint32_t VOFF = sb + 65536;         // Vh 16KB | Vl 16KB

    // --- Q load (64 rows x 256 cols; 4 panels of 64 cols) ---
#pragma unroll
    for (int i = 0; i < 16; i++) {
        const int lin = tid + 128 * i;            // 0..2047
        const int row = lin >> 5, u = lin & 31;
        CP_ASYNC16(QOFF + (u >> 3) * 8192 + sw128((uint32_t)(row * 128 + (u & 7) * 16)),
                   Qz + row * 32 + u);
    }
    CP_COMMIT();

    float accO1[16][4], accO2[16][4];
#pragma unroll
    for (int i = 0; i < 16; i++)
#pragma unroll
        for (int j = 0; j < 4; j++) { accO1[i][j] = 0.f; accO2[i][j] = 0.f; }
    float mr[2] = {-1e30f, -1e30f}, mi_[2] = {-1e30f, -1e30f};
    float lr[2] = {0.f, 0.f}, li[2] = {0.f, 0.f};

    auto issueK = [&](int c, int kb) {
        const int g = (c < 4) ? (c & 1) : (c - 2);
        const uint32_t kbuf = KOFF + (c & 1) * 16384;
#pragma unroll
        for (int i = 0; i < 8; i++) {
            const int lin = tid + 128 * i;        // 0..1023
            const int row = lin >> 3, seg = lin & 7;
            const int grow = kb * 64 + (row & 63) + ((row >> 6) << 10);
            CP_ASYNC16(kbuf + sw128((uint32_t)(row * 128 + seg * 16)),
                       Kz + (size_t)grow * 32 + g * 8 + seg);
        }
        CP_COMMIT();
    };

    constexpr float SC = 0.125f;

    for (int kb = 0; kb < 16; kb++) {
#pragma unroll
        for (int i = 0; i < 16; i++) {
            const int lin = tid + 128 * i;        // 0..2047
            const int half = lin >> 10, r2 = lin & 1023;
            const int row = r2 >> 3, seg = r2 & 7;
            CP_ASYNC16(VOFF + half * 16384 + sw128((uint32_t)(row * 128 + seg * 16)),
                       Vz + row * 256 + half * 128 + kb * 8 + seg);
        }
        CP_COMMIT();
        issueK(0, kb);

        float accS[16][4];
#pragma unroll
        for (int i = 0; i < 16; i++)
#pragma unroll
            for (int j = 0; j < 4; j++) accS[i][j] = 0.f;

        for (int c = 0; c < 6; c++) {
            CP_WAIT(0);
            __syncthreads();
            if (c < 5) issueK(c + 1, kb);
            const int pA = (c < 4) ? c : (c - 4);
            const uint32_t kbuf = KOFF + (c & 1) * 16384;
            const uint32_t qbase = QOFF + pA * 8192;
#pragma unroll
            for (int kk = 0; kk < 4; kk++) {
                uint32_t af[4];
                LDMX4(af, qbase + sw128((uint32_t)((16 * w + (lane & 15)) * 128
                                                   + kk * 32 + (lane >> 4) * 16)));
#pragma unroll
                for (int ntp = 0; ntp < 8; ntp++) {
                    uint32_t bfr[4];
                    LDMX4(bfr, kbuf + sw128((uint32_t)((ntp * 16 + (lane & 15)) * 128
                                                       + kk * 32 + (lane >> 4) * 16)));
                    mma_16816(accS[2 * ntp],     af, bfr[0], bfr[2]);
                    mma_16816(accS[2 * ntp + 1], af, bfr[1], bfr[3]);
                }
            }
        }

        float fr[2], fi[2];
#pragma unroll
        for (int g2 = 0; g2 < 2; g2++) {
            float a = -1e30f, b = -1e30f;
#pragma unroll
            for (int nt = 0; nt < 8; nt++) {
                a = fmaxf(a, fmaxf(accS[nt][2 * g2], accS[nt][2 * g2 + 1]));
                b = fmaxf(b, fmaxf(accS[nt + 8][2 * g2], accS[nt + 8][2 * g2 + 1]));
            }
            a = fmaxf(a, __shfl_xor_sync(0xffffffffu, a, 1));
            a = fmaxf(a, __shfl_xor_sync(0xffffffffu, a, 2));
            b = fmaxf(b, __shfl_xor_sync(0xffffffffu, b, 1));
            b = fmaxf(b, __shfl_xor_sync(0xffffffffu, b, 2));
            a *= SC; b *= SC;
            const float nmr = fmaxf(mr[g2], a);
            const float nmi = fmaxf(mi_[g2], b);
            fr[g2] = __expf(mr[g2] - nmr);
            fi[g2] = __expf(mi_[g2] - nmi);
            mr[g2] = nmr; mi_[g2] = nmi;
        }
#pragma unroll
        for (int nt = 0; nt < 16; nt++) {
            accO1[nt][0] *= fr[0]; accO1[nt][1] *= fr[0];
            accO1[nt][2] *= fr[1]; accO1[nt][3] *= fr[1];
            accO2[nt][0] *= fi[0]; accO2[nt][1] *= fi[0];
            accO2[nt][2] *= fi[1]; accO2[nt][3] *= fi[1];
        }

        uint32_t prh[4][4], pih[4][4];
        float sr0 = 0.f, sr1 = 0.f, si0 = 0.f, si1 = 0.f;
#pragma unroll
        for (int kk2 = 0; kk2 < 4; kk2++) {
            uint32_t prl[4], pil[4];
#pragma unroll
            for (int half = 0; half < 2; half++) {
                {
                    const int nt = 2 * kk2 + half;
                    const float p0 = __expf(accS[nt][0] * SC - mr[0]);
                    const float p1 = __expf(accS[nt][1] * SC - mr[0]);
                    const float p2 = __expf(accS[nt][2] * SC - mr[1]);
                    const float p3 = __expf(accS[nt][3] * SC - mr[1]);
                    sr0 += p0 + p1; sr1 += p2 + p3;
                    float l0, l1, l2, l3;
                    prh[kk2][2 * half]     = pack2(p0, p1, l0, l1);
                    prh[kk2][2 * half + 1] = pack2(p2, p3, l2, l3);
                    prl[2 * half]          = pack2n(l0, l1);
                    prl[2 * half + 1]      = pack2n(l2, l3);
                }
                {
                    const int nt = 8 + 2 * kk2 + half;
                    const float p0 = __expf(accS[nt][0] * SC - mi_[0]);
                    const float p1 = __expf(accS[nt][1] * SC - mi_[0]);
                    const float p2 = __expf(accS[nt][2] * SC - mi_[1]);
                    const float p3 = __expf(accS[nt][3] * SC - mi_[1]);
                    si0 += p0 + p1; si1 += p2 + p3;
                    float l0, l1, l2, l3;
                    pih[kk2][2 * half]     = pack2(p0, p1, l0, l1);
                    pih[kk2][2 * half + 1] = pack2(p2, p3, l2, l3);
                    pil[2 * half]          = pack2n(l0, l1);
                    pil[2 * half + 1]      = pack2n(l2, l3);
                }
            }
#pragma unroll
            for (int ntp = 0; ntp < 8; ntp++) {
                uint32_t bfr[4];
                LDMX4(bfr, VOFF + sw128((uint32_t)((ntp * 16 + (lane & 15)) * 128
                                                   + kk2 * 32 + (lane >> 4) * 16)));
                mma_16816(accO1[2 * ntp],     prh[kk2], bfr[0], bfr[2]);
                mma_16816(accO1[2 * ntp + 1], prh[kk2], bfr[1], bfr[3]);
                mma_16816(accO1[2 * ntp],     prl,      bfr[0], bfr[2]);
                mma_16816(accO1[2 * ntp + 1], prl,      bfr[1], bfr[3]);
                mma_16816(accO2[2 * ntp],     pih[kk2], bfr[0], bfr[2]);
                mma_16816(accO2[2 * ntp + 1], pih[kk2], bfr[1], bfr[3]);
                mma_16816(accO2[2 * ntp],     pil,      bfr[0], bfr[2]);
                mma_16816(accO2[2 * ntp + 1], pil,      bfr[1], bfr[3]);
            }
        }
        sr0 += __shfl_xor_sync(0xffffffffu, sr0, 1);
        sr0 += __shfl_xor_sync(0xffffffffu, sr0, 2);
        sr1 += __shfl_xor_sync(0xffffffffu, sr1, 1);
        sr1 += __shfl_xor_sync(0xffffffffu, sr1, 2);
        si0 += __shfl_xor_sync(0xffffffffu, si0, 1);
        si0 += __shfl_xor_sync(0xffffffffu, si0, 2);
        si1 += __shfl_xor_sync(0xffffffffu, si1, 1);
        si1 += __shfl_xor_sync(0xffffffffu, si1, 2);
        lr[0] = lr[0] * fr[0] + sr0;  lr[1] = lr[1] * fr[1] + sr1;
        li[0] = li[0] * fi[0] + si0;  li[1] = li[1] * fi[1] + si1;

#pragma unroll
        for (int kk2 = 0; kk2 < 4; kk2++)
#pragma unroll
            for (int ntp = 0; ntp < 8; ntp++) {
                uint32_t bfr[4];
                LDMX4(bfr, VOFF + 16384 + sw128((uint32_t)((ntp * 16 + (lane & 15)) * 128
                                                           + kk2 * 32 + (lane >> 4) * 16)));
                mma_16816(accO1[2 * ntp],     prh[kk2], bfr[0], bfr[2]);
                mma_16816(accO1[2 * ntp + 1], prh[kk2], bfr[1], bfr[3]);
                mma_16816(accO2[2 * ntp],     pih[kk2], bfr[0], bfr[2]);
                mma_16816(accO2[2 * ntp + 1], pih[kk2], bfr[1], bfr[3]);
            }

        __syncthreads();
    }

#pragma unroll
    for (int g2 = 0; g2 < 2; g2++) {
        const float ivr = 1.f / lr[g2];
        const float ivi = 1.f / li[g2];
        const int s = m0 + 16 * w + qrow + 8 * g2;
#pragma unroll
        for (int nt = 0; nt < 16; nt++) {
            const int dh = 4 * nt + ql;
            const float o_r = accO1[nt][2 * g2]     * ivr - accO2[nt][2 * g2 + 1] * ivi;
            const float o_i = accO1[nt][2 * g2 + 1] * ivr + accO2[nt][2 * g2]     * ivi;
            out[((size_t)(z >> 3) * 1024 + s) * 512 + (z & 7) * 64 + dh] =
                make_float2(o_r, o_i);
        }
    }
}

// ============================================================================
// V operand: planar fp32 [z][s][dh] -> g_vb [z][n=128][2048]
// ============================================================================
__global__ void __launch_bounds__(256)
vconv_kernel(const float* __restrict__ vr, const float* __restrict__ vi,
             __nv_bfloat16* __restrict__ vb)
{
    __shared__ float tile[2][64][65];
    const int z = blockIdx.y, s0 = blockIdx.x * 64;
    const int tid = threadIdx.x;
#pragma unroll
    for (int i = 0; i < 16; i++) {
        const int idx = tid + 256 * i;
        const int row = idx >> 6, c = idx & 63;
        const size_t g = ((size_t)z * 1024 + s0 + row) * 64 + c;
        tile[0][row][c] = vr[g];
        tile[1][row][c] = vi[g];
    }
    __syncthreads();
    const int r = tid >> 1, h4 = tid & 1;
    const int dh = r >> 1, ci = r & 1;
    __nv_bfloat16 hb[32], lb[32];
#pragma unroll
    for (int j = 0; j < 32; j++) {
        const int t = h4 * 32 + j;
        const float v = ci ? tile[1][t][dh] : tile[0][t][dh];
        const __nv_bfloat16 h = __float2bfloat16_rn(v);
        hb[j] = h;
        lb[j] = __float2bfloat16_rn(v - __bfloat162float(h));
    }
    const size_t base = ((size_t)z * 128 + r) * 2048 + s0 + h4 * 32;
#pragma unroll
    for (int u = 0; u < 4; u++) {
        *(uint4*)(vb + base + 8 * u) = pack8(hb + 8 * u);
        *(uint4*)(vb + base + 1024 + 8 * u) = pack8(lb + 8 * u);
    }
}

// ============================================================================
// fp32 -> bf16 hi/lo conversions (z-batched over up to 3 tensors)
// ============================================================================
__global__ void __launch_bounds__(256)
convx_kernel(const float2* __restrict__ in0, const float2* __restrict__ in1,
             const float2* __restrict__ in2,
             __nv_bfloat16* __restrict__ o0, __nv_bfloat16* __restrict__ o1,
             __nv_bfloat16* __restrict__ o2)
{
    const int zz = blockIdx.y;
    const float2* in = (zz == 0) ? in0 : (zz == 1) ? in1 : in2;
    __nv_bfloat16* out = (zz == 0) ? o0 : (zz == 1) ? o1 : o2;
    const int idx = blockIdx.x * 256 + threadIdx.x;
    const int m = idx >> 7;
    const int comp = (idx >> 6) & 1;
    const int f8 = (idx & 63) * 8;
    const float2* src = in + (long long)m * 512 + f8;
    __nv_bfloat16 hi[8], lo[8];
#pragma unroll
    for (int j = 0; j < 8; j++) {
        const float x = comp ? src[j].y : src[j].x;
        const __nv_bfloat16 h = __float2bfloat16_rn(x);
        hi[j] = h;
        lo[j] = __float2bfloat16_rn(x - __bfloat162float(h));
    }
    __nv_bfloat16* dst = out + (long long)m * 2048 + comp * 512 + f8;
    *(uint4*)dst = pack8(hi);
    *(uint4*)(dst + 1024) = pack8(lo);
}

__global__ void __launch_bounds__(256)
convw_kernel(const float* __restrict__ r0, const float* __restrict__ i0,
             const float* __restrict__ r1, const float* __restrict__ i1,
             const float* __restrict__ r2, const float* __restrict__ i2,
             __nv_bfloat16* __restrict__ o0, __nv_bfloat16* __restrict__ o1,
             __nv_bfloat16* __restrict__ o2)
{
    const int zz = blockIdx.y;
    const float* wr = (zz == 0) ? r0 : (zz == 1) ? r1 : r2;
    const float* wi = (zz == 0) ? i0 : (zz == 1) ? i1 : i2;
    __nv_bfloat16* out = (zz == 0) ? o0 : (zz == 1) ? o1 : o2;
    const int idx = blockIdx.x * 256 + threadIdx.x;
    const int n = idx >> 7;
    const int half = (idx >> 6) & 1;
    const int f8 = (idx & 63) * 8;
    const float* src;
    float sgn = 1.f;
    if (n < 512) { src = (half ? wi : wr) + (long long)n * 512; if (half) sgn = -1.f; }
    else         { src = (half ? wr : wi) + (long long)(n - 512) * 512; }
    __nv_bfloat16 hi[8], lo[8];
#pragma unroll
    for (int j = 0; j < 8; j++) {
        const float x = sgn * src[f8 + j];
        const __nv_bfloat16 h = __float2bfloat16_rn(x);
        hi[j] = h;
        lo[j] = __float2bfloat16_rn(x - __bfloat162float(h));
    }
    __nv_bfloat16* dst = out + (long long)n * 2048 + half * 512 + f8;
    *(uint4*)dst = pack8(hi);
    *(uint4*)(dst + 1024) = pack8(lo);
}

// ============================================================================
extern "C" void kernel_launch(void* const* d_in, const int* in_sizes, int n_in,
                              void* d_out, int out_size)
{
    (void)in_sizes; (void)n_in; (void)out_size;
    const float2* Qin = (const float2*)d_in[0];
    const float2* Kin = (const float2*)d_in[1];
    const float2* Vin = (const float2*)d_in[2];
    const float* wq_r = (const float*)d_in[3];
    const float* wq_i = (const float*)d_in[4];
    const float* wk_r = (const float*)d_in[5];
    const float* wk_i = (const float*)d_in[6];
    const float* wv_r = (const float*)d_in[7];
    const float* wv_i = (const float*)d_in[8];
    const float* wo_r = (const float*)d_in[9];
    const float* wo_i = (const float*)d_in[10];

    float *vr, *vi;
    float2 *o;
    __nv_bfloat16 *x2q, *x2k, *x2v, *x2o, *w2q, *w2k, *w2v, *w2o, *qb, *kb, *vb;
    cudaGetSymbolAddress((void**)&vr, g_vr);
    cudaGetSymbolAddress((void**)&vi, g_vi);
    cudaGetSymbolAddress((void**)&o, g_o);
    cudaGetSymbolAddress((void**)&x2q, g_x2q);
    cudaGetSymbolAddress((void**)&x2k, g_x2k);
    cudaGetSymbolAddress((void**)&x2v, g_x2v);
    cudaGetSymbolAddress((void**)&x2o, g_x2o);
    cudaGetSymbolAddress((void**)&w2q, g_w2q);
    cudaGetSymbolAddress((void**)&w2k, g_w2k);
    cudaGetSymbolAddress((void**)&w2v, g_w2v);
    cudaGetSymbolAddress((void**)&w2o, g_w2o);
    cudaGetSymbolAddress((void**)&qb, g_qb);
    cudaGetSymbolAddress((void**)&kb, g_kb);
    cudaGetSymbolAddress((void**)&vb, g_vb);

    cudaFuncSetAttribute(tgemm_kernel, cudaFuncAttributeMaxDynamicSharedMemorySize, SM_TOTAL);
    cudaFuncSetAttribute(fmha_kernel, cudaFuncAttributeMaxDynamicSharedMemorySize, SMF_TOTAL);

    // --- batched input + weight conversions ---
    convx_kernel<<<dim3(4096, 3), 256>>>(Qin, Kin, Vin, x2q, x2k, x2v);
    convw_kernel<<<dim3(512, 3), 256>>>(wq_r, wq_i, wk_r, wk_i, wv_r, wv_i,
                                        w2q, w2k, w2v);
    convw_kernel<<<dim3(512, 1), 256>>>(wo_r, wo_i, nullptr, nullptr, nullptr,
                                        nullptr, w2o, nullptr, nullptr);

    // --- Q/K/V projections in ONE z-batched launch (R13 config) ---
    tgemm_kernel<<<dim3(8, 64, 3), 256, SM_TOTAL>>>(
        (const uint4*)x2q, (const uint4*)x2k, (const uint4*)x2v,
        (const uint4*)w2q, (const uint4*)w2k, (const uint4*)w2v,
        /*obase=*/0, vr, vi, qb, kb);

    // --- V operand transpose ---
    vconv_kernel<<<dim3(16, 64), 256>>>(vr, vi, vb);

    // --- fused attention (64-row CTAs, 2/SM) ---
    fmha_kernel<<<dim3(16, 64), 128, SMF_TOTAL>>>(
        (const uint4*)qb, (const uint4*)kb, (const uint4*)vb, o);

    // --- output projection ---
    convx_kernel<<<dim3(4096, 1), 256>>>(o, nullptr, nullptr, x2o, nullptr, nullptr);
    tgemm_kernel<<<dim3(8, 64, 1), 256, SM_TOTAL>>>(
        (const uint4*)x2o, nullptr, nullptr,
        (const uint4*)w2o, nullptr, nullptr,
        /*obase=*/3, (float*)d_out, nullptr, nullptr, nullptr);
}

// round 16
// speedup vs baseline: 1.0882x; 1.0056x over previous
#include <cuda_runtime.h>
#include <cuda_bf16.h>
#include <cstdint>

// ============================================================================
// Problem constants
// ============================================================================
namespace {
constexpr int Bn = 8;
constexpr int Sn = 1024;
constexpr int Dn = 512;
constexpr int Hn = 8;
constexpr int Mproj = Bn * Sn;                                   // 8192

__device__ __nv_bfloat16 g_x2q[(long long)Mproj * 2048];  // act hi|lo per proj
__device__ __nv_bfloat16 g_x2k[(long long)Mproj * 2048];
__device__ __nv_bfloat16 g_x2v[(long long)Mproj * 2048];
__device__ __nv_bfloat16 g_x2o[(long long)Mproj * 2048];  // fmha out (bf16 hi|lo)
__device__ __nv_bfloat16 g_w2q[(long long)1024 * 2048];   // wgt hi|lo per proj
__device__ __nv_bfloat16 g_w2k[(long long)1024 * 2048];
__device__ __nv_bfloat16 g_w2v[(long long)1024 * 2048];
__device__ __nv_bfloat16 g_w2o[(long long)1024 * 2048];
__device__ __nv_bfloat16 g_qb[(long long)64 * 1024 * 256];  // Q score-operand
__device__ __nv_bfloat16 g_kb[(long long)64 * 2048 * 256];  // K: re rows | im rows
__device__ __nv_bfloat16 g_vb[(long long)64 * 128 * 2048];  // V operand (direct)
}

// ============================================================================
// Base-target PTX helpers
// ============================================================================
__device__ __forceinline__ uint32_t smem_u32(const void* p) {
    uint32_t a;
    asm("{ .reg .u64 t; cvta.to.shared.u64 t, %1; cvt.u32.u64 %0, t; }"
        : "=r"(a) : "l"(p));
    return a;
}
__device__ __forceinline__ uint32_t sw128(uint32_t off) {
    return off ^ ((off >> 3) & 0x70);
}
#define LDMX4(r, addr)                                                        \
    asm volatile("ldmatrix.sync.aligned.m8n8.x4.shared.b16 {%0,%1,%2,%3}, [%4];" \
        : "=r"((r)[0]), "=r"((r)[1]), "=r"((r)[2]), "=r"((r)[3]) : "r"(addr))
__device__ __forceinline__ void mma_16816(float* d, const uint32_t* a,
                                          uint32_t b0, uint32_t b1) {
    asm volatile(
        "mma.sync.aligned.m16n8k16.row.col.f32.bf16.bf16.f32 "
        "{%0,%1,%2,%3}, {%4,%5,%6,%7}, {%8,%9}, {%0,%1,%2,%3};"
        : "+f"(d[0]), "+f"(d[1]), "+f"(d[2]), "+f"(d[3])
        : "r"(a[0]), "r"(a[1]), "r"(a[2]), "r"(a[3]), "r"(b0), "r"(b1));
}
#define CP_ASYNC16(dst, src) \
    asm volatile("cp.async.cg.shared.global [%0], [%1], 16;" :: "r"(dst), "l"(src))
#define CP_COMMIT()     asm volatile("cp.async.commit_group;" ::: "memory")
#define CP_WAIT(n)      asm volatile("cp.async.wait_group %0;" :: "n"(n) : "memory")

namespace {
constexpr int SM_BUF = 32768;                // A(16K)+B(16K) per buffer
constexpr int SM_TOTAL = 2 * SM_BUF + 1024;
constexpr int SMF_TOTAL = 98304 + 1024;      // fmha64: Q 32K + K 32K + V 32K
}

__device__ __forceinline__ uint4 pack8(const __nv_bfloat16* v) {
    union { __nv_bfloat16 b[8]; uint4 u; } P;
#pragma unroll
    for (int i = 0; i < 8; i++) P.b[i] = v[i];
    return P.u;
}
__device__ __forceinline__ uint32_t pack2(float x, float y, float& lx, float& ly) {
    __nv_bfloat16 hx = __float2bfloat16_rn(x);
    __nv_bfloat16 hy = __float2bfloat16_rn(y);
    lx = x - __bfloat162float(hx);
    ly = y - __bfloat162float(hy);
    unsigned short ux = *reinterpret_cast<unsigned short*>(&hx);
    unsigned short uy = *reinterpret_cast<unsigned short*>(&hy);
    return (uint32_t)ux | ((uint32_t)uy << 16);
}
__device__ __forceinline__ uint32_t pack2n(float x, float y) {
    __nv_bfloat16 hx = __float2bfloat16_rn(x);
    __nv_bfloat16 hy = __float2bfloat16_rn(y);
    unsigned short ux = *reinterpret_cast<unsigned short*>(&hx);
    unsigned short uy = *reinterpret_cast<unsigned short*>(&hy);
    return (uint32_t)ux | ((uint32_t)uy << 16);
}

// ============================================================================
// Projection GEMM (R13 config: 8 warps 2x4, warp tile 64x32, 256 thr, 2 CTA/SM)
//   omode 0: Q -> g_qb; 1: K -> g_kb (re|im rows);
//   omode 2: V -> g_vb bf16 hi/lo DIRECT (fused, replaces vconv);
//   omode 3: d_out interleaved fp32
// ============================================================================
__device__ __forceinline__ void store_proj_rt(int omode, float v, int m, int n,
    __nv_bfloat16* qb, __nv_bfloat16* kb, __nv_bfloat16* vbp, float* f0)
{
    const int comp = n >> 9, f = n & 511, hh = f >> 6, dh = f & 63;
    if (omode == 3) {
        f0[(size_t)m * 1024 + (size_t)f * 2 + comp] = v;
        return;
    }
    const int z = ((m >> 10) << 3) + hh;
    const int s = m & 1023;
    const __nv_bfloat16 h = __float2bfloat16_rn(v);
    const __nv_bfloat16 l = __float2bfloat16_rn(v - __bfloat162float(h));
    if (omode == 2) {
        // vb[z][r=2*dh+comp][s] = hi, [s+1024] = lo
        const size_t base = ((size_t)z * 128 + 2 * dh + comp) * 2048 + s;
        vbp[base] = h; vbp[base + 1024] = l;
        return;
    }
    if (omode == 0) {
        const size_t base = ((size_t)z * 1024 + s) * 256 + comp * 64 + dh;
        qb[base] = h; qb[base + 128] = l;
    } else {
        // real form at row s, imag form at row 1024+s
        const size_t r0 = ((size_t)z * 2048 + s) * 256;
        const size_t r1 = ((size_t)z * 2048 + 1024 + s) * 256;
        if (comp == 0) {
            kb[r0 + dh] = h;       kb[r0 + 128 + dh] = l;
            kb[r1 + 64 + dh] = h;  kb[r1 + 192 + dh] = l;
        } else {
            kb[r0 + 64 + dh] = __hneg(h); kb[r0 + 192 + dh] = __hneg(l);
            kb[r1 + dh] = h;       kb[r1 + 128 + dh] = l;
        }
    }
}

__global__ void __launch_bounds__(256, 2)
tgemm_kernel(const uint4* __restrict__ a0, const uint4* __restrict__ a1,
             const uint4* __restrict__ a2,
             const uint4* __restrict__ w0, const uint4* __restrict__ w1,
             const uint4* __restrict__ w2,
             int obase,
             float* __restrict__ f0,
             __nv_bfloat16* __restrict__ qb, __nv_bfloat16* __restrict__ kb,
             __nv_bfloat16* __restrict__ vbp)
{
    extern __shared__ char smem[];
    const uint32_t sbase = (smem_u32(smem) + 1023) & ~1023u;
    const int tid = threadIdx.x;
    const int lane = tid & 31, wid = tid >> 5;
    const int wm = wid & 1, wn = wid >> 1;
    const int m0 = blockIdx.y * 128, n0 = blockIdx.x * 128;
    const int zz = blockIdx.z;
    const int omode = obase + zz;
    const uint4* A2 = (zz == 0) ? a0 : (zz == 1) ? a1 : a2;
    const uint4* B2 = (zz == 0) ? w0 : (zz == 1) ? w1 : w2;

    float acc[4][4][4];
#pragma unroll
    for (int i = 0; i < 4; i++)
#pragma unroll
        for (int j = 0; j < 4; j++)
#pragma unroll
            for (int k = 0; k < 4; k++) acc[i][j][k] = 0.f;

    auto issue_chunk = [&](int c, int buf) {
        const int pass = c >> 4;
        const int kc = (c & 15) << 6;
        const int ca = (kc + ((pass == 1) ? 1024 : 0)) >> 3;
        const int cb = (kc + ((pass == 2) ? 1024 : 0)) >> 3;
        const uint32_t ab = sbase + buf * SM_BUF;
        const uint32_t bb = ab + 16384;
#pragma unroll
        for (int i = 0; i < 4; i++) {
            const int lin = tid + 256 * i;
            const int row = lin >> 3, seg = lin & 7;
            const uint32_t off = sw128((uint32_t)(row * 128 + seg * 16));
            CP_ASYNC16(ab + off, &A2[(size_t)(m0 + row) * 256 + ca + seg]);
            CP_ASYNC16(bb + off, &B2[(size_t)(n0 + row) * 256 + cb + seg]);
        }
        CP_COMMIT();
    };

    constexpr int NC = 48;
    issue_chunk(0, 0);
    for (int c = 0; c < NC; c++) {
        const int buf = c & 1;
        if (c + 1 < NC) { issue_chunk(c + 1, buf ^ 1); CP_WAIT(1); }
        else            { CP_WAIT(0); }
        __syncthreads();
        const uint32_t ab = sbase + buf * SM_BUF;
        const uint32_t bb = ab + 16384;
#pragma unroll
        for (int kk = 0; kk < 4; kk++) {
            uint32_t af[4][4];
#pragma unroll
            for (int mt = 0; mt < 4; mt++) {
                const int row = wm * 64 + mt * 16 + (lane & 15);
                LDMX4(af[mt], ab + sw128((uint32_t)(row * 128 + kk * 32 + (lane >> 4) * 16)));
            }
            uint32_t bfr[2][4];
#pragma unroll
            for (int p = 0; p < 2; p++) {
                const int row = wn * 32 + p * 16 + (lane & 15);
                LDMX4(bfr[p], bb + sw128((uint32_t)(row * 128 + kk * 32 + (lane >> 4) * 16)));
            }
#pragma unroll
            for (int mt = 0; mt < 4; mt++)
#pragma unroll
                for (int nt = 0; nt < 4; nt++)
                    mma_16816(acc[mt][nt], af[mt],
                              bfr[nt >> 1][nt & 1], bfr[nt >> 1][(nt & 1) + 2]);
        }
        __syncthreads();
    }

    const int qrow = lane >> 2, qcol = (lane & 3) * 2;
#pragma unroll
    for (int mt = 0; mt < 4; mt++)
#pragma unroll
        for (int nt = 0; nt < 4; nt++)
#pragma unroll
            for (int h2 = 0; h2 < 2; h2++) {
                const int m = m0 + wm * 64 + mt * 16 + qrow + 8 * h2;
                const int n = n0 + wn * 32 + nt * 8 + qcol;
                store_proj_rt(omode, acc[mt][nt][2 * h2],     m, n,     qb, kb, vbp, f0);
                store_proj_rt(omode, acc[mt][nt][2 * h2 + 1], m, n + 1, qb, kb, vbp, f0);
            }
}

// ============================================================================
// Fused flash attention — 64-row CTAs (4 warps, 2 CTAs/SM), R8 engine.
// Output fused: writes g_x2o bf16 hi/lo layout directly (no fp32 bounce).
// ============================================================================
__global__ void __launch_bounds__(128, 2)
fmha_kernel(const uint4* __restrict__ qb4, const uint4* __restrict__ kb4,
            const uint4* __restrict__ vb4, __nv_bfloat16* __restrict__ xout)
{
    extern __shared__ char smem[];
    const uint32_t sb = (smem_u32(smem) + 1023) & ~1023u;
    const int tid = threadIdx.x;
    const int lane = tid & 31, w = tid >> 5;      // w = 0..3
    const int qrow = lane >> 2, ql = lane & 3;
    const int z = blockIdx.y;
    const int m0 = blockIdx.x * 64;

    const uint4* Qz = qb4 + ((size_t)z * 1024 + m0) * 32;
    const uint4* Kz = kb4 + (size_t)z * 2048 * 32;
    const uint4* Vz = vb4 + (size_t)z * 128 * 256;

    const uint32_t QOFF = sb;                 // 4 panels x 8KB (64 rows)
    const uint32_t KOFF = sb + 32768;         // 2 x 16KB
    const uint32_t VOFF = sb + 65536;         // Vh 16KB | Vl 16KB

    // --- Q load (64 rows x 256 cols; 4 panels of 64 cols) ---
#pragma unroll
    for (int i = 0; i < 16; i++) {
        const int lin = tid + 128 * i;            // 0..2047
        const int row = lin >> 5, u = lin & 31;
        CP_ASYNC16(QOFF + (u >> 3) * 8192 + sw128((uint32_t)(row * 128 + (u & 7) * 16)),
                   Qz + row * 32 + u);
    }
    CP_COMMIT();

    float accO1[16][4], accO2[16][4];
#pragma unroll
    for (int i = 0; i < 16; i++)
#pragma unroll
        for (int j = 0; j < 4; j++) { accO1[i][j] = 0.f; accO2[i][j] = 0.f; }
    float mr[2] = {-1e30f, -1e30f}, mi_[2] = {-1e30f, -1e30f};
    float lr[2] = {0.f, 0.f}, li[2] = {0.f, 0.f};

    auto issueK = [&](int c, int kb) {
        const int g = (c < 4) ? (c & 1) : (c - 2);
        const uint32_t kbuf = KOFF + (c & 1) * 16384;
#pragma unroll
        for (int i = 0; i < 8; i++) {
            const int lin = tid + 128 * i;        // 0..1023
            const int row = lin >> 3, seg = lin & 7;
            const int grow = kb * 64 + (row & 63) + ((row >> 6) << 10);
            CP_ASYNC16(kbuf + sw128((uint32_t)(row * 128 + seg * 16)),
                       Kz + (size_t)grow * 32 + g * 8 + seg);
        }
        CP_COMMIT();
    };

    constexpr float SC = 0.125f;

    for (int kb = 0; kb < 16; kb++) {
#pragma unroll
        for (int i = 0; i < 16; i++) {
            const int lin = tid + 128 * i;        // 0..2047
            const int half = lin >> 10, r2 = lin & 1023;
            const int row = r2 >> 3, seg = r2 & 7;
            CP_ASYNC16(VOFF + half * 16384 + sw128((uint32_t)(row * 128 + seg * 16)),
                       Vz + row * 256 + half * 128 + kb * 8 + seg);
        }
        CP_COMMIT();
        issueK(0, kb);

        float accS[16][4];
#pragma unroll
        for (int i = 0; i < 16; i++)
#pragma unroll
            for (int j = 0; j < 4; j++) accS[i][j] = 0.f;

        for (int c = 0; c < 6; c++) {
            CP_WAIT(0);
            __syncthreads();
            if (c < 5) issueK(c + 1, kb);
            const int pA = (c < 4) ? c : (c - 4);
            const uint32_t kbuf = KOFF + (c & 1) * 16384;
            const uint32_t qbase = QOFF + pA * 8192;
#pragma unroll
            for (int kk = 0; kk < 4; kk++) {
                uint32_t af[4];
                LDMX4(af, qbase + sw128((uint32_t)((16 * w + (lane & 15)) * 128
                                                   + kk * 32 + (lane >> 4) * 16)));
#pragma unroll
                for (int ntp = 0; ntp < 8; ntp++) {
                    uint32_t bfr[4];
                    LDMX4(bfr, kbuf + sw128((uint32_t)((ntp * 16 + (lane & 15)) * 128
                                                       + kk * 32 + (lane >> 4) * 16)));
                    mma_16816(accS[2 * ntp],     af, bfr[0], bfr[2]);
                    mma_16816(accS[2 * ntp + 1], af, bfr[1], bfr[3]);
                }
            }
        }

        float fr[2], fi[2];
#pragma unroll
        for (int g2 = 0; g2 < 2; g2++) {
            float a = -1e30f, b = -1e30f;
#pragma unroll
            for (int nt = 0; nt < 8; nt++) {
                a = fmaxf(a, fmaxf(accS[nt][2 * g2], accS[nt][2 * g2 + 1]));
                b = fmaxf(b, fmaxf(accS[nt + 8][2 * g2], accS[nt + 8][2 * g2 + 1]));
            }
            a = fmaxf(a, __shfl_xor_sync(0xffffffffu, a, 1));
            a = fmaxf(a, __shfl_xor_sync(0xffffffffu, a, 2));
            b = fmaxf(b, __shfl_xor_sync(0xffffffffu, b, 1));
            b = fmaxf(b, __shfl_xor_sync(0xffffffffu, b, 2));
            a *= SC; b *= SC;
            const float nmr = fmaxf(mr[g2], a);
            const float nmi = fmaxf(mi_[g2], b);
            fr[g2] = __expf(mr[g2] - nmr);
            fi[g2] = __expf(mi_[g2] - nmi);
            mr[g2] = nmr; mi_[g2] = nmi;
        }
#pragma unroll
        for (int nt = 0; nt < 16; nt++) {
            accO1[nt][0] *= fr[0]; accO1[nt][1] *= fr[0];
            accO1[nt][2] *= fr[1]; accO1[nt][3] *= fr[1];
            accO2[nt][0] *= fi[0]; accO2[nt][1] *= fi[0];
            accO2[nt][2] *= fi[1]; accO2[nt][3] *= fi[1];
        }

        uint32_t prh[4][4], pih[4][4];
        float sr0 = 0.f, sr1 = 0.f, si0 = 0.f, si1 = 0.f;
#pragma unroll
        for (int kk2 = 0; kk2 < 4; kk2++) {
            uint32_t prl[4], pil[4];
#pragma unroll
            for (int half = 0; half < 2; half++) {
                {
                    const int nt = 2 * kk2 + half;
                    const float p0 = __expf(accS[nt][0] * SC - mr[0]);
                    const float p1 = __expf(accS[nt][1] * SC - mr[0]);
                    const float p2 = __expf(accS[nt][2] * SC - mr[1]);
                    const float p3 = __expf(accS[nt][3] * SC - mr[1]);
                    sr0 += p0 + p1; sr1 += p2 + p3;
                    float l0, l1, l2, l3;
                    prh[kk2][2 * half]     = pack2(p0, p1, l0, l1);
                    prh[kk2][2 * half + 1] = pack2(p2, p3, l2, l3);
                    prl[2 * half]          = pack2n(l0, l1);
                    prl[2 * half + 1]      = pack2n(l2, l3);
                }
                {
                    const int nt = 8 + 2 * kk2 + half;
                    const float p0 = __expf(accS[nt][0] * SC - mi_[0]);
                    const float p1 = __expf(accS[nt][1] * SC - mi_[0]);
                    const float p2 = __expf(accS[nt][2] * SC - mi_[1]);
                    const float p3 = __expf(accS[nt][3] * SC - mi_[1]);
                    si0 += p0 + p1; si1 += p2 + p3;
                    float l0, l1, l2, l3;
                    pih[kk2][2 * half]     = pack2(p0, p1, l0, l1);
                    pih[kk2][2 * half + 1] = pack2(p2, p3, l2, l3);
                    pil[2 * half]          = pack2n(l0, l1);
                    pil[2 * half + 1]      = pack2n(l2, l3);
                }
            }
#pragma unroll
            for (int ntp = 0; ntp < 8; ntp++) {
                uint32_t bfr[4];
                LDMX4(bfr, VOFF + sw128((uint32_t)((ntp * 16 + (lane & 15)) * 128
                                                   + kk2 * 32 + (lane >> 4) * 16)));
                mma_16816(accO1[2 * ntp],     prh[kk2], bfr[0], bfr[2]);
                mma_16816(accO1[2 * ntp + 1], prh[kk2], bfr[1], bfr[3]);
                mma_16816(accO1[2 * ntp],     prl,      bfr[0], bfr[2]);
                mma_16816(accO1[2 * ntp + 1], prl,      bfr[1], bfr[3]);
                mma_16816(accO2[2 * ntp],     pih[kk2], bfr[0], bfr[2]);
                mma_16816(accO2[2 * ntp + 1], pih[kk2], bfr[1], bfr[3]);
                mma_16816(accO2[2 * ntp],     pil,      bfr[0], bfr[2]);
                mma_16816(accO2[2 * ntp + 1], pil,      bfr[1], bfr[3]);
            }
        }
        sr0 += __shfl_xor_sync(0xffffffffu, sr0, 1);
        sr0 += __shfl_xor_sync(0xffffffffu, sr0, 2);
        sr1 += __shfl_xor_sync(0xffffffffu, sr1, 1);
        sr1 += __shfl_xor_sync(0xffffffffu, sr1, 2);
        si0 += __shfl_xor_sync(0xffffffffu, si0, 1);
        si0 += __shfl_xor_sync(0xffffffffu, si0, 2);
        si1 += __shfl_xor_sync(0xffffffffu, si1, 1);
        si1 += __shfl_xor_sync(0xffffffffu, si1, 2);
        lr[0] = lr[0] * fr[0] + sr0;  lr[1] = lr[1] * fr[1] + sr1;
        li[0] = li[0] * fi[0] + si0;  li[1] = li[1] * fi[1] + si1;

#pragma unroll
        for (int kk2 = 0; kk2 < 4; kk2++)
#pragma unroll
            for (int ntp = 0; ntp < 8; ntp++) {
                uint32_t bfr[4];
                LDMX4(bfr, VOFF + 16384 + sw128((uint32_t)((ntp * 16 + (lane & 15)) * 128
                                                           + kk2 * 32 + (lane >> 4) * 16)));
                mma_16816(accO1[2 * ntp],     prh[kk2], bfr[0], bfr[2]);
                mma_16816(accO1[2 * ntp + 1], prh[kk2], bfr[1], bfr[3]);
                mma_16816(accO2[2 * ntp],     pih[kk2], bfr[0], bfr[2]);
                mma_16816(accO2[2 * ntp + 1], pih[kk2], bfr[1], bfr[3]);
            }

        __syncthreads();
    }

    // --- epilogue: combine, normalize, write x2o bf16 hi/lo DIRECT ---
#pragma unroll
    for (int g2 = 0; g2 < 2; g2++) {
        const float ivr = 1.f / lr[g2];
        const float ivi = 1.f / li[g2];
        const int s = m0 + 16 * w + qrow + 8 * g2;
        const size_t rowb = ((size_t)(z >> 3) * 1024 + s) * 2048 + (z & 7) * 64;
#pragma unroll
        for (int nt = 0; nt < 16; nt++) {
            const int dh = 4 * nt + ql;
            const float o_r = accO1[nt][2 * g2]     * ivr - accO2[nt][2 * g2 + 1] * ivi;
            const float o_i = accO1[nt][2 * g2 + 1] * ivr + accO2[nt][2 * g2]     * ivi;
            const __nv_bfloat16 hr = __float2bfloat16_rn(o_r);
            const __nv_bfloat16 hi_ = __float2bfloat16_rn(o_i);
            const size_t base = rowb + dh;
            xout[base]        = hr;
            xout[base + 512]  = hi_;
            xout[base + 1024] = __float2bfloat16_rn(o_r - __bfloat162float(hr));
            xout[base + 1536] = __float2bfloat16_rn(o_i - __bfloat162float(hi_));
        }
    }
}

// ============================================================================
// fp32 -> bf16 hi/lo conversions (z-batched over up to 3 tensors)
// ============================================================================
__global__ void __launch_bounds__(256)
convx_kernel(const float2* __restrict__ in0, const float2* __restrict__ in1,
             const float2* __restrict__ in2,
             __nv_bfloat16* __restrict__ o0, __nv_bfloat16* __restrict__ o1,
             __nv_bfloat16* __restrict__ o2)
{
    const int zz = blockIdx.y;
    const float2* in = (zz == 0) ? in0 : (zz == 1) ? in1 : in2;
    __nv_bfloat16* out = (zz == 0) ? o0 : (zz == 1) ? o1 : o2;
    const int idx = blockIdx.x * 256 + threadIdx.x;
    const int m = idx >> 7;
    const int comp = (idx >> 6) & 1;
    const int f8 = (idx & 63) * 8;
    const float2* src = in + (long long)m * 512 + f8;
    __nv_bfloat16 hi[8], lo[8];
#pragma unroll
    for (int j = 0; j < 8; j++) {
        const float x = comp ? src[j].y : src[j].x;
        const __nv_bfloat16 h = __float2bfloat16_rn(x);
        hi[j] = h;
        lo[j] = __float2bfloat16_rn(x - __bfloat162float(h));
    }
    __nv_bfloat16* dst = out + (long long)m * 2048 + comp * 512 + f8;
    *(uint4*)dst = pack8(hi);
    *(uint4*)(dst + 1024) = pack8(lo);
}

__global__ void __launch_bounds__(256)
convw_kernel(const float* __restrict__ r0, const float* __restrict__ i0,
             const float* __restrict__ r1, const float* __restrict__ i1,
             const float* __restrict__ r2, const float* __restrict__ i2,
             __nv_bfloat16* __restrict__ o0, __nv_bfloat16* __restrict__ o1,
             __nv_bfloat16* __restrict__ o2)
{
    const int zz = blockIdx.y;
    const float* wr = (zz == 0) ? r0 : (zz == 1) ? r1 : r2;
    const float* wi = (zz == 0) ? i0 : (zz == 1) ? i1 : i2;
    __nv_bfloat16* out = (zz == 0) ? o0 : (zz == 1) ? o1 : o2;
    const int idx = blockIdx.x * 256 + threadIdx.x;
    const int n = idx >> 7;
    const int half = (idx >> 6) & 1;
    const int f8 = (idx & 63) * 8;
    const float* src;
    float sgn = 1.f;
    if (n < 512) { src = (half ? wi : wr) + (long long)n * 512; if (half) sgn = -1.f; }
    else         { src = (half ? wr : wi) + (long long)(n - 512) * 512; }
    __nv_bfloat16 hi[8], lo[8];
#pragma unroll
    for (int j = 0; j < 8; j++) {
        const float x = sgn * src[f8 + j];
        const __nv_bfloat16 h = __float2bfloat16_rn(x);
        hi[j] = h;
        lo[j] = __float2bfloat16_rn(x - __bfloat162float(h));
    }
    __nv_bfloat16* dst = out + (long long)n * 2048 + half * 512 + f8;
    *(uint4*)dst = pack8(hi);
    *(uint4*)(dst + 1024) = pack8(lo);
}

// ============================================================================
extern "C" void kernel_launch(void* const* d_in, const int* in_sizes, int n_in,
                              void* d_out, int out_size)
{
    (void)in_sizes; (void)n_in; (void)out_size;
    const float2* Qin = (const float2*)d_in[0];
    const float2* Kin = (const float2*)d_in[1];
    const float2* Vin = (const float2*)d_in[2];
    const float* wq_r = (const float*)d_in[3];
    const float* wq_i = (const float*)d_in[4];
    const float* wk_r = (const float*)d_in[5];
    const float* wk_i = (const float*)d_in[6];
    const float* wv_r = (const float*)d_in[7];
    const float* wv_i = (const float*)d_in[8];
    const float* wo_r = (const float*)d_in[9];
    const float* wo_i = (const float*)d_in[10];

    __nv_bfloat16 *x2q, *x2k, *x2v, *x2o, *w2q, *w2k, *w2v, *w2o, *qb, *kb, *vb;
    cudaGetSymbolAddress((void**)&x2q, g_x2q);
    cudaGetSymbolAddress((void**)&x2k, g_x2k);
    cudaGetSymbolAddress((void**)&x2v, g_x2v);
    cudaGetSymbolAddress((void**)&x2o, g_x2o);
    cudaGetSymbolAddress((void**)&w2q, g_w2q);
    cudaGetSymbolAddress((void**)&w2k, g_w2k);
    cudaGetSymbolAddress((void**)&w2v, g_w2v);
    cudaGetSymbolAddress((void**)&w2o, g_w2o);
    cudaGetSymbolAddress((void**)&qb, g_qb);
    cudaGetSymbolAddress((void**)&kb, g_kb);
    cudaGetSymbolAddress((void**)&vb, g_vb);

    cudaFuncSetAttribute(tgemm_kernel, cudaFuncAttributeMaxDynamicSharedMemorySize, SM_TOTAL);
    cudaFuncSetAttribute(fmha_kernel, cudaFuncAttributeMaxDynamicSharedMemorySize, SMF_TOTAL);

    // --- batched input + weight conversions ---
    convx_kernel<<<dim3(4096, 3), 256>>>(Qin, Kin, Vin, x2q, x2k, x2v);
    convw_kernel<<<dim3(512, 3), 256>>>(wq_r, wq_i, wk_r, wk_i, wv_r, wv_i,
                                        w2q, w2k, w2v);
    convw_kernel<<<dim3(512, 1), 256>>>(wo_r, wo_i, nullptr, nullptr, nullptr,
                                        nullptr, w2o, nullptr, nullptr);

    // --- Q/K/V projections; V writes vb directly (vconv fused away) ---
    tgemm_kernel<<<dim3(8, 64, 3), 256, SM_TOTAL>>>(
        (const uint4*)x2q, (const uint4*)x2k, (const uint4*)x2v,
        (const uint4*)w2q, (const uint4*)w2k, (const uint4*)w2v,
        /*obase=*/0, nullptr, qb, kb, vb);

    // --- fused attention (64-row CTAs, 2/SM); writes x2o bf16 directly ---
    fmha_kernel<<<dim3(16, 64), 128, SMF_TOTAL>>>(
        (const uint4*)qb, (const uint4*)kb, (const uint4*)vb, x2o);

    // --- output projection (reads x2o, no conversion kernel needed) ---
    tgemm_kernel<<<dim3(8, 64, 1), 256, SM_TOTAL>>>(
        (const uint4*)x2o, nullptr, nullptr,
        (const uint4*)w2o, nullptr, nullptr,
        /*obase=*/3, (float*)d_out, nullptr, nullptr, nullptr);
}